// round 5
// baseline (speedup 1.0000x reference)
#include <cuda_runtime.h>

#define N 1024

// Order-preserving float -> uint32 mapping (exact, bijective, monotone).
__device__ __forceinline__ unsigned fkey(float f) {
    unsigned k = __float_as_uint(f);
    return (k & 0x80000000u) ? ~k : (k | 0x80000000u);
}
__device__ __forceinline__ float funkey(unsigned k) {
    unsigned b = (k & 0x80000000u) ? (k & 0x7fffffffu) : ~k;
    return __uint_as_float(b);
}

// Exact LAPJV: column reduction + 2x augmenting row reduction warm start,
// then shortest augmenting paths (1 barrier / Dijkstra settle).
// One block, one thread per column. C(i,j) = ||a_i - b_j|| on the fly.
__global__ __launch_bounds__(1024, 1)
void emd_jv_kernel(const float* __restrict__ gt,
                   const float* __restrict__ gen,
                   float* __restrict__ out) {
    __shared__ float4 s_row[N];                 // {ax, ay, az, u}
    __shared__ int    s_p[N];                   // p[j] = row matched to col j (-1 free)
    __shared__ int    s_claim[N];               // CR row claims
    __shared__ unsigned short s_way[N];         // predecessor column on alt path
    __shared__ unsigned long long s_best[3];    // phase-3 slots (key<<32|j<<11|p+1)
    __shared__ unsigned long long s_bA[2], s_bB[2];  // ARR min1/min2 slots
    __shared__ int    s_free[N], s_free2[N];
    __shared__ int    s_nfree, s_ibid;
    __shared__ float  s_sum[32];

    const int j    = threadIdx.x;
    const int lane = j & 31;
    const int wid  = j >> 5;

    s_row[j] = make_float4(gt[3 * j], gt[3 * j + 1], gt[3 * j + 2], 0.0f);
    s_p[j]     = -1;
    s_claim[j] = 0x7fffffff;
    const float bx = gen[3 * j], by = gen[3 * j + 1], bz = gen[3 * j + 2];
    if (j < 3) s_best[j] = ~0ull;
    if (j < 2) { s_bA[j] = ~0ull; s_bB[j] = ~0ull; }
    __syncthreads();

    // ---- phase 1: column reduction ----
    float v = 3.0e38f;
    int   bi = 0;
    for (int i = 0; i < N; ++i) {
        const float4 row = s_row[i];
        const float dx = row.x - bx, dy = row.y - by, dz = row.z - bz;
        const float d2 = fmaf(dx, dx, fmaf(dy, dy, dz * dz));
        const float c  = d2 * rsqrtf(fmaxf(d2, 1e-30f));
        if (c < v) { v = c; bi = i; }
    }
    atomicMin(&s_claim[bi], j);
    __syncthreads();
    if (s_claim[bi] == j) s_p[j] = bi;
    if (j == 0) {                               // build free-row list (deterministic)
        int n = 0;
        for (int i = 0; i < N; ++i)
            if (s_claim[i] == 0x7fffffff) s_free[n++] = i;
        s_nfree = n;
    }
    __syncthreads();

    // ---- phase 2: augmenting row reduction (2 passes) ----
    for (int pass = 0; pass < 2; ++pass) {
        int cur = 0, nnew = 0, steps = 0;       // live on thread 0 only
        const int nfree = s_nfree;
        if (j == 0) s_ibid = (nfree > 0) ? s_free[cur++] : -1;
        __syncthreads();

        int par = 0;
        while (true) {
            const int i = s_ibid;
            if (i < 0) break;

            const float4 row = s_row[i];
            const float dx = row.x - bx, dy = row.y - by, dz = row.z - bz;
            const float d2 = fmaf(dx, dx, fmaf(dy, dy, dz * dz));
            const float c  = d2 * rsqrtf(fmaxf(d2, 1e-30f));
            const unsigned key = fkey(c - v);

            // min1
            unsigned wmin = __reduce_min_sync(0xffffffffu, key);
            unsigned bal  = __ballot_sync(0xffffffffu, key == wmin);
            if (lane == (__ffs(bal) - 1))
                atomicMin(&s_bA[par], ((unsigned long long)wmin << 32) | (unsigned)j);
            __syncthreads();                              // B1
            const unsigned long long a = s_bA[par];
            const int j1 = (int)(a & 0xffffffffu);

            // min2 (exclude j1)
            const unsigned key2 = (j == j1) ? 0xffffffffu : key;
            wmin = __reduce_min_sync(0xffffffffu, key2);
            bal  = __ballot_sync(0xffffffffu, key2 == wmin);
            if (wmin != 0xffffffffu && lane == (__ffs(bal) - 1))
                atomicMin(&s_bB[par], ((unsigned long long)wmin << 32) | (unsigned)j);
            __syncthreads();                              // B2
            const unsigned long long b = s_bB[par];
            const int j2 = (int)(b & 0xffffffffu);
            const bool lower = (unsigned)(a >> 32) < (unsigned)(b >> 32);

            int jass = j1;
            int i0   = s_p[j1];
            if (!lower && i0 >= 0) { jass = j2; i0 = s_p[j2]; }

            if (lower && j == j1)
                v -= funkey((unsigned)(b >> 32)) - funkey((unsigned)(a >> 32));

            if (j == 0) {
                s_p[jass] = i;
                ++steps;
                if (i0 >= 0) {
                    if (lower && steps < 3 * N) s_free[--cur] = i0;  // reprocess next
                    else                        s_free2[nnew++] = i0; // defer
                }
                s_ibid = (cur < nfree) ? s_free[cur++] : -1;
            }
            par ^= 1;
            if (j == 0) { s_bA[par] = ~0ull; s_bB[par] = ~0ull; }
            __syncthreads();                              // B3
        }
        if (j == 0) s_nfree = nnew;
        __syncthreads();
        for (int t = j; t < s_nfree; t += N) s_free[t] = s_free2[t];
        __syncthreads();
    }

    // ---- u init: u[i] = c(i, col(i)) - v[col(i)] for matched rows ----
    {
        const int i = s_p[j];
        if (i >= 0) {
            const float4 row = s_row[i];
            const float dx = row.x - bx, dy = row.y - by, dz = row.z - bz;
            const float d2 = fmaf(dx, dx, fmaf(dy, dy, dz * dz));
            const float c  = d2 * rsqrtf(fmaxf(d2, 1e-30f));
            s_row[i].w = c - v;
        }
    }
    __syncthreads();
    const int nf2 = s_nfree;

    // ---- phase 3: shortest augmenting path per remaining free row ----
    int par = 0;
    for (int f = 0; f < nf2; ++f) {
        const int i = s_free[f];
        __syncthreads();                        // prev augment + dual writes visible

        float M   = 3.0e38f;
        float D   = 0.0f;
        int   i0  = i;
        int   j0  = N;
        const int pj = s_p[j];
        bool  used = false;
        float Dj = 0.0f;
        int   pown = 0;
        int   j1f; float Dfinal;

        while (true) {
            unsigned key = 0xffffffffu;
            if (!used) {
                const float4 row = s_row[i0];
                const float dx = row.x - bx, dy = row.y - by, dz = row.z - bz;
                const float d2 = fmaf(dx, dx, fmaf(dy, dy, dz * dz));
                const float c  = d2 * rsqrtf(fmaxf(d2, 1e-30f));
                const float cand = (c - row.w - v) + D;
                if (cand < M) { M = cand; s_way[j] = (unsigned short)j0; }
                key = fkey(M);
            }

            const unsigned wmin = __reduce_min_sync(0xffffffffu, key);
            const unsigned bal  = __ballot_sync(0xffffffffu, key == wmin);
            if (wmin != 0xffffffffu && lane == (__ffs(bal) - 1))
                atomicMin(&s_best[par],
                          ((unsigned long long)wmin << 32)
                          | ((unsigned)j << 11) | (unsigned)(pj + 1));
            if (j == 0) s_best[par + 1 == 3 ? 0 : par + 1] = ~0ull;
            __syncthreads();

            const unsigned long long best = s_best[par];
            par = (par + 1 == 3) ? 0 : par + 1;
            const float Dn  = funkey((unsigned)(best >> 32));
            const int   j1  = (int)((best >> 11) & 0x3ffu);
            const int   i0n = (int)(best & 0x7ffu) - 1;

            if (j == j1 && i0n >= 0) { used = true; Dj = Dn; pown = i0n; }
            if (i0n < 0) { j1f = j1; Dfinal = Dn; break; }
            i0 = i0n; D = Dn; j0 = j1;
        }

        if (used) { v += Dj - Dfinal; s_row[pown].w += Dfinal - Dj; }
        if (j == 0) {
            s_row[i].w += Dfinal;
            int jj = j1f;
            while (true) {
                const int jw = s_way[jj];
                if (jw == N) { s_p[jj] = i; break; }
                s_p[jj] = s_p[jw];
                jj = jw;
            }
        }
    }
    __syncthreads();

    // ---- mean of matched distances (exact sqrt) ----
    const int pi = s_p[j];
    const float4 row = s_row[pi];
    const float dx = row.x - bx, dy = row.y - by, dz = row.z - bz;
    float acc = sqrtf(fmaf(dx, dx, fmaf(dy, dy, dz * dz)));
    #pragma unroll
    for (int o = 16; o; o >>= 1) acc += __shfl_down_sync(0xffffffffu, acc, o);
    if (lane == 0) s_sum[wid] = acc;
    __syncthreads();
    if (j == 0) {
        float s = 0.0f;
        #pragma unroll
        for (int w = 0; w < 32; ++w) s += s_sum[w];
        out[0] = s * (1.0f / (float)N);
    }
}

extern "C" void kernel_launch(void* const* d_in, const int* in_sizes, int n_in,
                              void* d_out, int out_size) {
    const float* gt  = (const float*)d_in[0];   // (1,1024,3) fp32
    const float* gen = (const float*)d_in[1];   // (1,1024,3) fp32
    (void)in_sizes; (void)n_in; (void)out_size;
    emd_jv_kernel<<<1, 1024>>>(gt, gen, (float*)d_out);
}

// round 6
// speedup vs baseline: 1.1008x; 1.1008x over previous
#include <cuda_runtime.h>

#define N 1024
#define T 512            // threads; each owns columns t and t+T

// Order-preserving float -> uint32 mapping (exact, bijective, monotone).
__device__ __forceinline__ unsigned fkey(float f) {
    unsigned k = __float_as_uint(f);
    return (k & 0x80000000u) ? ~k : (k | 0x80000000u);
}
__device__ __forceinline__ float funkey(unsigned k) {
    unsigned b = (k & 0x80000000u) ? (k & 0x7fffffffu) : ~k;
    return __uint_as_float(b);
}
__device__ __forceinline__ float fdist(float4 row, float bx, float by, float bz) {
    const float dx = row.x - bx, dy = row.y - by, dz = row.z - bz;
    const float d2 = fmaf(dx, dx, fmaf(dy, dy, dz * dz));
    float c;
    asm("sqrt.approx.f32 %0, %1;" : "=f"(c) : "f"(d2));
    return c;
}

// Exact LAPJV: column-reduction warm start + shortest augmenting paths
// (1 barrier per Dijkstra settle). One block, 512 threads x 2 columns.
__global__ __launch_bounds__(T, 1)
void emd_jv_kernel(const float* __restrict__ gt,
                   const float* __restrict__ gen,
                   float* __restrict__ out) {
    __shared__ float4 s_row[N];                 // {ax, ay, az, u}
    __shared__ int    s_p[N];                   // p[j] = row matched to col j (-1 free)
    __shared__ int    s_claim[N];               // CR row claims
    __shared__ unsigned short s_way[N];         // predecessor column on alt path
    __shared__ unsigned long long s_best[3];    // (key<<32 | j<<11 | p+1), triple-buffered
    __shared__ float  s_sum[T / 32];

    const int t    = threadIdx.x;
    const int lane = t & 31;
    const int wid  = t >> 5;
    const int jc0  = t, jc1 = t + T;

    // ---- init / load points ----
    float bx[2], by[2], bz[2];
    #pragma unroll
    for (int k = 0; k < 2; ++k) {
        const int r = t + k * T;
        s_row[r] = make_float4(gt[3 * r], gt[3 * r + 1], gt[3 * r + 2], 0.0f);
        s_p[r] = -1;
        s_claim[r] = 0x7fffffff;
        bx[k] = gen[3 * r]; by[k] = gen[3 * r + 1]; bz[k] = gen[3 * r + 2];
    }
    if (t < 3) s_best[t] = ~0ull;
    __syncthreads();

    // ---- phase 1: column reduction (v[j] = min_i C(i,j), claim argmin rows) ----
    float v[2] = {3.0e38f, 3.0e38f};
    int   bi[2] = {0, 0};
    for (int i = 0; i < N; ++i) {
        const float4 row = s_row[i];
        #pragma unroll
        for (int k = 0; k < 2; ++k) {
            const float c = fdist(row, bx[k], by[k], bz[k]);
            if (c < v[k]) { v[k] = c; bi[k] = i; }
        }
    }
    atomicMin(&s_claim[bi[0]], jc0);
    atomicMin(&s_claim[bi[1]], jc1);
    __syncthreads();
    if (s_claim[bi[0]] == jc0) s_p[jc0] = bi[0];
    if (s_claim[bi[1]] == jc1) s_p[jc1] = bi[1];
    __syncthreads();

    int par = 0;

    // ---- phase 2: shortest augmenting path for each free row ----
    for (int i = 0; i < N; ++i) {
        if (s_claim[i] != 0x7fffffff) continue; // pre-matched (uniform branch)
        __syncthreads();                        // prev augment + dual writes visible

        float M[2]  = {3.0e38f, 3.0e38f};
        bool  used[2] = {false, false};
        float Dj[2]; int pown[2];
        const int pj[2] = {s_p[jc0], s_p[jc1]}; // stable during the search
        float D  = 0.0f;
        int   i0 = i, j0 = N;
        int   j1f; float Dfinal;

        while (true) {
            // ---- relax my free columns from (i0, D) ----
            const float4 row = s_row[i0];       // one LDS.128 broadcast
            #pragma unroll
            for (int k = 0; k < 2; ++k) {
                if (!used[k]) {
                    const float c = fdist(row, bx[k], by[k], bz[k]);
                    const float cand = (c - row.w - v[k]) + D;
                    if (cand < M[k]) {
                        M[k] = cand;
                        s_way[t + k * T] = (unsigned short)j0;
                    }
                }
            }
            const unsigned k0 = used[0] ? 0xffffffffu : fkey(M[0]);
            const unsigned k1 = used[1] ? 0xffffffffu : fkey(M[1]);
            unsigned key; unsigned long long pay;
            if (k0 <= k1) {                     // ties -> lower column index
                key = k0;
                pay = ((unsigned long long)k0 << 32) | ((unsigned)jc0 << 11)
                      | (unsigned)(pj[0] + 1);
            } else {
                key = k1;
                pay = ((unsigned long long)k1 << 32) | ((unsigned)jc1 << 11)
                      | (unsigned)(pj[1] + 1);
            }

            // ---- exact argmin: warp REDUX, direct atomicMin (no ballot) ----
            const unsigned wmin = __reduce_min_sync(0xffffffffu, key);
            if (key == wmin && wmin != 0xffffffffu)
                atomicMin(&s_best[par], pay);
            if (t == 0) s_best[par + 1 == 3 ? 0 : par + 1] = ~0ull;
            __syncthreads();                    // the one barrier

            const unsigned long long best = s_best[par];
            par = (par + 1 == 3) ? 0 : par + 1;
            const float Dn  = funkey((unsigned)(best >> 32));
            const int   j1  = (int)((best >> 11) & 0x3ffu);
            const int   i0n = (int)(best & 0x7ffu) - 1;

            if (i0n >= 0) {
                if (j1 == jc0) { used[0] = true; Dj[0] = Dn; pown[0] = i0n; }
                if (j1 == jc1) { used[1] = true; Dj[1] = Dn; pown[1] = i0n; }
            } else {
                j1f = j1; Dfinal = Dn;
                break;
            }
            i0 = i0n; D = Dn; j0 = j1;
        }

        // ---- post-search dual updates (once per search) ----
        #pragma unroll
        for (int k = 0; k < 2; ++k)
            if (used[k]) {
                v[k] += Dj[k] - Dfinal;
                s_row[pown[k]].w += Dfinal - Dj[k];   // distinct rows: no conflict
            }
        if (t == 0) {
            s_row[i].w += Dfinal;               // u of newly assigned row
            int jj = j1f;                       // augment alternating path
            while (true) {
                const int jw = s_way[jj];
                if (jw == N) { s_p[jj] = i; break; }
                s_p[jj] = s_p[jw];
                jj = jw;
            }
        }
    }
    __syncthreads();

    // ---- mean of matched distances (exact sqrt) ----
    float acc = 0.0f;
    #pragma unroll
    for (int k = 0; k < 2; ++k) {
        const int jcol = t + k * T;
        const float4 row = s_row[s_p[jcol]];
        const float dx = row.x - bx[k], dy = row.y - by[k], dz = row.z - bz[k];
        acc += sqrtf(fmaf(dx, dx, fmaf(dy, dy, dz * dz)));
    }
    #pragma unroll
    for (int o = 16; o; o >>= 1) acc += __shfl_down_sync(0xffffffffu, acc, o);
    if (lane == 0) s_sum[wid] = acc;
    __syncthreads();
    if (t == 0) {
        float s = 0.0f;
        #pragma unroll
        for (int w = 0; w < T / 32; ++w) s += s_sum[w];
        out[0] = s * (1.0f / (float)N);
    }
}

extern "C" void kernel_launch(void* const* d_in, const int* in_sizes, int n_in,
                              void* d_out, int out_size) {
    const float* gt  = (const float*)d_in[0];   // (1,1024,3) fp32
    const float* gen = (const float*)d_in[1];   // (1,1024,3) fp32
    (void)in_sizes; (void)n_in; (void)out_size;
    emd_jv_kernel<<<1, T>>>(gt, gen, (float*)d_out);
}